// round 15
// baseline (speedup 1.0000x reference)
#include <cuda_runtime.h>
#include <cuda_fp16.h>
#include <mma.h>

using namespace nvcuda;

// ---------------------------------------------------------------------------
// GCN_13898514169996: 2-layer GCN, N=100000, E=3.2M, 512->16->7.
// gcn(h)[v] = dinv[v] * ( sum_{u->v} h[u]*dinv[u] + h[v]*dinv[v] ) + b
// dinv = rsqrt(cnt[v]+1). edge_index int32.
// Round 15: gemm1 runs after count and writes dinv-scaled fp16 hs directly
// (k_scale + hsraw eliminated). scan+place fork against gemm1.
// ---------------------------------------------------------------------------

#define MAXN  100000
#define MAXE  3200000

__device__ uint4 g_hs  [MAXN * 2];    // (X@W1)*dinv as 16 halves/row
__device__ uint4 g_hs2 [MAXN];        // (h1@W2)*dinv as 7 halves + pad
__device__ int   g_cnt [MAXN];
__device__ int   g_off [MAXN];
__device__ int   g_ord [MAXE];
__device__ int   g_eadj[MAXE];
__device__ unsigned long long g_scanpack[512];

__device__ __forceinline__ void acc8(float* acc, uint4 u) {
    float2 f;
    f = __half22float2(*(__half2*)&u.x); acc[0] += f.x; acc[1] += f.y;
    f = __half22float2(*(__half2*)&u.y); acc[2] += f.x; acc[3] += f.y;
    f = __half22float2(*(__half2*)&u.z); acc[4] += f.x; acc[5] += f.y;
    f = __half22float2(*(__half2*)&u.w); acc[6] += f.x; acc[7] += f.y;
}
__device__ __forceinline__ void unpack8(float* f, uint4 u) {
    float2 t;
    t = __half22float2(*(__half2*)&u.x); f[0] = t.x; f[1] = t.y;
    t = __half22float2(*(__half2*)&u.y); f[2] = t.x; f[3] = t.y;
    t = __half22float2(*(__half2*)&u.z); f[4] = t.x; f[5] = t.y;
    t = __half22float2(*(__half2*)&u.w); f[6] = t.x; f[7] = t.y;
}

// ---- zero counts + scan flags ------------------------------------------------------
__global__ void k_zero(int n) {
    int v = blockIdx.x * blockDim.x + threadIdx.x;
    if (v < n) g_cnt[v] = 0;
    if (v < 512) g_scanpack[v] = 0ull;
}

// ---- in-degree count, 4 edges/thread; keep the returned ordinal --------------------
__global__ void k_count(const int* __restrict__ dst, int E) {
    int i = blockIdx.x * blockDim.x + threadIdx.x;
    int e0 = i * 4;
    if (e0 + 3 < E) {
        int4 d = __ldg((const int4*)dst + i);
        int4 o;
        o.x = atomicAdd(&g_cnt[d.x], 1);
        o.y = atomicAdd(&g_cnt[d.y], 1);
        o.z = atomicAdd(&g_cnt[d.z], 1);
        o.w = atomicAdd(&g_cnt[d.w], 1);
        *((int4*)g_ord + i) = o;
    } else {
        for (int e = e0; e < E; e++)
            g_ord[e] = atomicAdd(&g_cnt[dst[e]], 1);
    }
}

// ---- single-pass exclusive scan (decoupled lookback) -------------------------------
__global__ void __launch_bounds__(256) k_scan(int n) {
    __shared__ int warp_tot[8];
    __shared__ int s_excl;
    int t = threadIdx.x, b = blockIdx.x;
    int v = b * 256 + t;
    int val = (v < n) ? g_cnt[v] : 0;

    int lane = t & 31, w = t >> 5;
    int x = val;
    #pragma unroll
    for (int d = 1; d < 32; d <<= 1) {
        int y = __shfl_up_sync(0xffffffffu, x, d);
        if (lane >= d) x += y;
    }
    if (lane == 31) warp_tot[w] = x;
    __syncthreads();
    if (w == 0) {
        int wt = (lane < 8) ? warp_tot[lane] : 0;
        #pragma unroll
        for (int d = 1; d < 8; d <<= 1) {
            int y = __shfl_up_sync(0xffffffffu, wt, d);
            if (lane >= d) wt += y;
        }
        if (lane < 8) warp_tot[lane] = wt;
    }
    __syncthreads();

    int local_excl  = x - val + ((w > 0) ? warp_tot[w - 1] : 0);
    int block_total = warp_tot[7];

    if (t == 0) {
        atomicExch(&g_scanpack[b], ((unsigned long long)block_total << 2) | 1ull);
        long long run = 0;
        int j = b - 1;
        while (j >= 0) {
            unsigned long long pk;
            do { pk = atomicAdd(&g_scanpack[j], 0ull); } while ((pk & 3ull) == 0ull);
            run += (long long)(pk >> 2);
            if ((pk & 3ull) == 2ull) break;
            j--;
        }
        s_excl = (int)run;
        atomicExch(&g_scanpack[b],
                   ((unsigned long long)(run + block_total) << 2) | 2ull);
    }
    __syncthreads();

    if (v < n) g_off[v] = s_excl + local_excl;
}

// ---- CSR placement, atomic-free: slot = off[dst] + ord ------------------------------
__global__ void k_place(const int* __restrict__ src,
                        const int* __restrict__ dst, int E) {
    int i = blockIdx.x * blockDim.x + threadIdx.x;
    int e0 = i * 4;
    if (e0 + 3 < E) {
        int4 d = __ldg((const int4*)dst + i);
        int4 s = __ldg((const int4*)src + i);
        int4 o = *((const int4*)g_ord + i);
        g_eadj[g_off[d.x] + o.x] = s.x;
        g_eadj[g_off[d.y] + o.y] = s.y;
        g_eadj[g_off[d.z] + o.z] = s.z;
        g_eadj[g_off[d.w] + o.w] = s.w;
    } else {
        for (int e = e0; e < E; e++)
            g_eadj[g_off[dst[e]] + g_ord[e]] = src[e];
    }
}

// ---- GEMM1 on tensor cores: g_hs = fp16( (X @ W1) * dinv ) -------------------------
// 128 threads = 4 warps; 64 rows/block; K chunked at 64. Epilogue stages the
// fp32 tile in smem, scales by dinv and quantizes to fp16 in one pass.
__global__ void __launch_bounds__(128) k_gemm1(const float* __restrict__ x,
                                               const float* __restrict__ W1,
                                               int n) {
    __shared__ __half Xh[64][72];   // 64 rows x 64 k halves, pad 8 (16B)
    __shared__ __half Wh[64][16];   // k x j chunk
    __shared__ float  Os[64][16];   // fp32 output staging

    int t    = threadIdx.x;
    int warp = t >> 5;
    int lane = t & 31;
    int row0 = blockIdx.x * 64;

    wmma::fragment<wmma::accumulator, 16, 16, 16, float> cfrag;
    wmma::fill_fragment(cfrag, 0.f);

    #pragma unroll 1
    for (int ch = 0; ch < 8; ch++) {
        int k0 = ch * 64;
        __syncthreads();
        #pragma unroll
        for (int u = 0; u < 8; u++) {
            int idx = t + u * 128;
            int kk = idx >> 4, jj = idx & 15;
            Wh[kk][jj] = __float2half(W1[(size_t)(k0 + kk) * 16 + jj]);
        }
        #pragma unroll
        for (int u = 0; u < 8; u++) {
            int idx = t + u * 128;
            int rl = idx >> 4;
            int kq = (idx & 15) * 4;
            int gr = row0 + rl; if (gr > n - 1) gr = n - 1;
            float4 v = __ldg((const float4*)(x + (size_t)gr * 512 + k0 + kq));
            Xh[rl][kq + 0] = __float2half(v.x);
            Xh[rl][kq + 1] = __float2half(v.y);
            Xh[rl][kq + 2] = __float2half(v.z);
            Xh[rl][kq + 3] = __float2half(v.w);
        }
        __syncthreads();

        #pragma unroll
        for (int ks = 0; ks < 4; ks++) {
            wmma::fragment<wmma::matrix_a, 16, 16, 16, __half, wmma::row_major> afrag;
            wmma::fragment<wmma::matrix_b, 16, 16, 16, __half, wmma::row_major> bfrag;
            wmma::load_matrix_sync(afrag, &Xh[warp * 16][ks * 16], 72);
            wmma::load_matrix_sync(bfrag, &Wh[ks * 16][0], 16);
            wmma::mma_sync(cfrag, afrag, bfrag, cfrag);
        }
    }

    // epilogue: stage fp32 tile in smem, then scale+quantize to fp16
    wmma::store_matrix_sync(&Os[warp * 16][0], cfrag, 16, wmma::mem_row_major);
    __syncwarp();

    int rl = warp * 16 + (lane >> 1);   // local row handled by this lane
    int hq = lane & 1;                  // feature half (0..7 or 8..15)
    int row = row0 + rl;
    if (row < n) {
        float dv = rsqrtf((float)g_cnt[row] + 1.f);
        const float* p = &Os[rl][hq * 8];
        __half2 h0 = __float22half2_rn(make_float2(p[0] * dv, p[1] * dv));
        __half2 h1 = __float22half2_rn(make_float2(p[2] * dv, p[3] * dv));
        __half2 h2 = __float22half2_rn(make_float2(p[4] * dv, p[5] * dv));
        __half2 h3 = __float22half2_rn(make_float2(p[6] * dv, p[7] * dv));
        uint4 u;
        u.x = *(unsigned*)&h0; u.y = *(unsigned*)&h1;
        u.z = *(unsigned*)&h2; u.w = *(unsigned*)&h3;
        g_hs[(size_t)row * 2 + hq] = u;
    }
}

// ---- fused gather1 + layer-1 epilogue + layer-2 GEMM (2 threads/node) ---------------
__global__ void __launch_bounds__(256) k_gl1(const float* __restrict__ b1,
                                             const float* __restrict__ W2,
                                             int n) {
    __shared__ float W2s[112];
    __shared__ float b1s[16];
    int t = threadIdx.x;
    if (t < 112) W2s[t] = W2[t];
    if (t < 16)  b1s[t] = b1[t];
    __syncthreads();

    int gi = blockIdx.x * 256 + t;
    int v  = gi >> 1;
    if (v >= n) return;
    int q   = gi & 1;                 // features q*8 .. q*8+7
    int off = g_off[v];
    int cnt = g_cnt[v];

    float acc[8];
    #pragma unroll
    for (int j = 0; j < 8; j++) acc[j] = 0.f;

    int i = 0;
    for (; i + 4 <= cnt; i += 4) {
        int s0 = g_eadj[off + i + 0];
        int s1 = g_eadj[off + i + 1];
        int s2 = g_eadj[off + i + 2];
        int s3 = g_eadj[off + i + 3];
        uint4 u0 = g_hs[(size_t)s0 * 2 + q];
        uint4 u1 = g_hs[(size_t)s1 * 2 + q];
        uint4 u2 = g_hs[(size_t)s2 * 2 + q];
        uint4 u3 = g_hs[(size_t)s3 * 2 + q];
        acc8(acc, u0); acc8(acc, u1); acc8(acc, u2); acc8(acc, u3);
    }
    for (; i < cnt; i++) {
        int s0 = g_eadj[off + i];
        acc8(acc, g_hs[(size_t)s0 * 2 + q]);
    }

    float dv = rsqrtf((float)cnt + 1.f);
    float self[8];
    unpack8(self, g_hs[(size_t)v * 2 + q]);

    float h[8];
    #pragma unroll
    for (int j = 0; j < 8; j++)
        h[j] = fmaxf(fmaf(dv, acc[j] + self[j], b1s[q * 8 + j]), 0.f);

    float o[7];
    #pragma unroll
    for (int j = 0; j < 7; j++) {
        const float* wq = W2s + (q * 8) * 7 + j;
        float s = h[0] * wq[0];
        s += h[1] * wq[7];
        s += h[2] * wq[14];
        s += h[3] * wq[21];
        s += h[4] * wq[28];
        s += h[5] * wq[35];
        s += h[6] * wq[42];
        s += h[7] * wq[49];
        o[j] = s;
    }
    #pragma unroll
    for (int j = 0; j < 7; j++)
        o[j] += __shfl_xor_sync(0xffffffffu, o[j], 1);

    if (q == 0) {
        __half2 p0 = __float22half2_rn(make_float2(o[0] * dv, o[1] * dv));
        __half2 p1 = __float22half2_rn(make_float2(o[2] * dv, o[3] * dv));
        __half2 p2 = __float22half2_rn(make_float2(o[4] * dv, o[5] * dv));
        __half2 p3 = __float22half2_rn(make_float2(o[6] * dv, 0.f));
        uint4 u;
        u.x = *(unsigned*)&p0; u.y = *(unsigned*)&p1;
        u.z = *(unsigned*)&p2; u.w = *(unsigned*)&p3;
        g_hs2[v] = u;
    }
}

// ---- fused gather2 + final (1 thread/node) ------------------------------------------
__global__ void __launch_bounds__(256) k_gl2(const float* __restrict__ b2,
                                             float* __restrict__ out, int n) {
    int v = blockIdx.x * 256 + threadIdx.x;
    if (v >= n) return;
    int off = g_off[v];
    int cnt = g_cnt[v];

    float acc[8];
    #pragma unroll
    for (int j = 0; j < 8; j++) acc[j] = 0.f;

    int i = 0;
    for (; i + 4 <= cnt; i += 4) {
        int s0 = g_eadj[off + i + 0];
        int s1 = g_eadj[off + i + 1];
        int s2 = g_eadj[off + i + 2];
        int s3 = g_eadj[off + i + 3];
        uint4 u0 = g_hs2[s0];
        uint4 u1 = g_hs2[s1];
        uint4 u2 = g_hs2[s2];
        uint4 u3 = g_hs2[s3];
        acc8(acc, u0); acc8(acc, u1); acc8(acc, u2); acc8(acc, u3);
    }
    for (; i < cnt; i++) acc8(acc, g_hs2[g_eadj[off + i]]);

    float dv = rsqrtf((float)cnt + 1.f);
    float self[8];
    unpack8(self, g_hs2[v]);

    float m[7];
    #pragma unroll
    for (int j = 0; j < 7; j++)
        m[j] = fmaf(dv, acc[j] + self[j], __ldg(b2 + j));

    float mx = m[0];
    #pragma unroll
    for (int j = 1; j < 7; j++) mx = fmaxf(mx, m[j]);
    float s = 0.f;
    #pragma unroll
    for (int j = 0; j < 7; j++) s += expf(m[j] - mx);
    float l = logf(s) + mx;

    float* ov = out + (size_t)v * 7;
    #pragma unroll
    for (int j = 0; j < 7; j++) ov[j] = m[j] - l;
}

// ---------------------------------------------------------------------------
extern "C" void kernel_launch(void* const* d_in, const int* in_sizes, int n_in,
                              void* d_out, int out_size) {
    const float* x  = (const float*)d_in[0];
    const int*   ei = (const int*)d_in[1];      // int32 (JAX x64 disabled)
    const float* W1 = (const float*)d_in[2];
    const float* b1 = (const float*)d_in[3];
    const float* W2 = (const float*)d_in[4];
    const float* b2 = (const float*)d_in[5];

    int n = in_sizes[0] / 512;     // 100000
    int E = in_sizes[1] / 2;       // 3200000
    const int* src = ei;
    const int* dst = ei + E;

    static cudaStream_t s2 = 0;
    static cudaEvent_t evCnt = 0, evJoin = 0;
    if (!s2) {
        cudaStreamCreateWithFlags(&s2, cudaStreamNonBlocking);
        cudaEventCreateWithFlags(&evCnt, cudaEventDisableTiming);
        cudaEventCreateWithFlags(&evJoin, cudaEventDisableTiming);
    }

    int nb  = (n + 255) / 256;
    int e4  = (E + 3) / 4;
    int eb4 = (e4 + 255) / 256;

    // serial prefix: counts (needed by both sides)
    k_zero <<<nb, 256>>>(n);
    k_count<<<eb4, 256>>>(dst, E);
    cudaEventRecord(evCnt, 0);

    // side stream: scan + place — overlaps gemm1
    cudaStreamWaitEvent(s2, evCnt, 0);
    k_scan <<<nb, 256, 0, s2>>>(n);
    k_place<<<eb4, 256, 0, s2>>>(src, dst, E);
    cudaEventRecord(evJoin, s2);

    // main stream: gemm1 writes dinv-scaled fp16 hs directly
    k_gemm1<<<(n + 63) / 64, 128>>>(x, W1, n);
    cudaStreamWaitEvent(0, evJoin, 0);

    k_gl1<<<(2 * n + 255) / 256, 256>>>(b1, W2, n);
    k_gl2<<<(n + 255) / 256, 256>>>(b2, (float*)d_out, n);
}